// round 5
// baseline (speedup 1.0000x reference)
#include <cuda_runtime.h>
#include <math.h>
#include <stdint.h>

// ---------------------------------------------------------------------------
// Problem constants
// ---------------------------------------------------------------------------
#define NSAMP  8192      // N rows
#define NDIMT  3072      // flattened image dim
#define NKER   64        // number of patches
#define NSUB   48        // dims per patch (== K) -> Q_k is square orthogonal
#define MKNOT  200       // spline knots per transformed coord
#define NTRT   3072      // NKER * NSUB

// ---------------------------------------------------------------------------
// Device scratch (static allocation only; no cudaMalloc anywhere)
// ---------------------------------------------------------------------------
__device__ float g_Q [NKER * NSUB * NSUB];   // orthogonalized blocks, row-major [k][j][i]
__device__ float g_xx[NTRT * MKNOT];         // x knots
__device__ float g_yy[NTRT * MKNOT];         // y knots
__device__ float g_dl[NTRT * MKNOT];         // derivatives (delta)
__device__ float g_lj[NKER * NSAMP];         // per-(kernel,row) logdet partials

// ---------------------------------------------------------------------------
// Kernel 1: per-patch modified Gram-Schmidt QR (equals qr() Q with
// positive-diagonal sign convention). 64 blocks, 64 threads (48 active).
// ---------------------------------------------------------------------------
__global__ void orth_kernel(const float* __restrict__ A_raw) {
    const int k   = blockIdx.x;
    const int tid = threadIdx.x;
    __shared__ float qcol[NSUB];

    float col[NSUB];
    const float* Ab = A_raw + k * (NSUB * NSUB);
    if (tid < NSUB) {
#pragma unroll
        for (int r = 0; r < NSUB; ++r) col[r] = Ab[r * NSUB + tid];
    }

    for (int c = 0; c < NSUB; ++c) {
        if (tid == c) {
            float nrm = 0.f;
#pragma unroll
            for (int r = 0; r < NSUB; ++r) nrm += col[r] * col[r];
            float inv = 1.0f / sqrtf(nrm);
#pragma unroll
            for (int r = 0; r < NSUB; ++r) { col[r] *= inv; qcol[r] = col[r]; }
        }
        __syncthreads();
        if (tid < NSUB) {
            if (tid == c) {
                float* gq = g_Q + k * (NSUB * NSUB);
#pragma unroll
                for (int r = 0; r < NSUB; ++r) gq[r * NSUB + c] = qcol[r];
            } else if (tid > c) {
                float dot = 0.f;
#pragma unroll
                for (int r = 0; r < NSUB; ++r) dot += qcol[r] * col[r];
#pragma unroll
                for (int r = 0; r < NSUB; ++r) col[r] -= dot * qcol[r];
            }
        }
        __syncthreads();
    }
}

// ---------------------------------------------------------------------------
// Kernel 2: build spline knot tables. One warp per transformed coordinate t.
// Inclusive warp scans over exp(logdx)/exp(logdy); delta = exp(logderiv).
// ---------------------------------------------------------------------------
__global__ void knots_kernel(const float* __restrict__ x0,
                             const float* __restrict__ logdx,
                             const float* __restrict__ y0,
                             const float* __restrict__ logdy,
                             const float* __restrict__ logderiv) {
    const int warp = (blockIdx.x * blockDim.x + threadIdx.x) >> 5;
    const int lane = threadIdx.x & 31;
    if (warp >= NTRT) return;

    // xx scan
    {
        float carry = x0[warp];
        if (lane == 0) g_xx[warp * MKNOT] = carry;
        const float* src = logdx + (size_t)warp * (MKNOT - 1);
        for (int c = 0; c < MKNOT - 1; c += 32) {
            int m = c + lane;
            float v = (m < MKNOT - 1) ? expf(src[m]) : 0.f;
#pragma unroll
            for (int off = 1; off < 32; off <<= 1) {
                float o = __shfl_up_sync(0xffffffffu, v, off);
                if (lane >= off) v += o;
            }
            if (m < MKNOT - 1) g_xx[warp * MKNOT + m + 1] = carry + v;
            carry += __shfl_sync(0xffffffffu, v, 31);
        }
    }
    // yy scan
    {
        float carry = y0[warp];
        if (lane == 0) g_yy[warp * MKNOT] = carry;
        const float* src = logdy + (size_t)warp * (MKNOT - 1);
        for (int c = 0; c < MKNOT - 1; c += 32) {
            int m = c + lane;
            float v = (m < MKNOT - 1) ? expf(src[m]) : 0.f;
#pragma unroll
            for (int off = 1; off < 32; off <<= 1) {
                float o = __shfl_up_sync(0xffffffffu, v, off);
                if (lane >= off) v += o;
            }
            if (m < MKNOT - 1) g_yy[warp * MKNOT + m + 1] = carry + v;
            carry += __shfl_sync(0xffffffffu, v, 31);
        }
    }
    // delta
    for (int m = lane; m < MKNOT; m += 32)
        g_dl[warp * MKNOT + m] = expf(logderiv[(size_t)warp * MKNOT + m]);
}

// ---------------------------------------------------------------------------
// Kernel 3: fused gather -> GEMV fwd -> RQ spline -> GEMV back -> scatter.
// Grid: (64 kernels, 16 row-chunks). Block: 384 threads, 4 iterations of
// 128 rows each. ~223 KB dynamic smem.
// ---------------------------------------------------------------------------
#define TPB      384
#define ROWS_IT  128
#define ITERS    4      // 4 * 128 = 512 rows per block; grid.y = 16

// smem layout (float offsets)
#define SO_XX 0                       // 48 x 201  (padded, conflict-free search)
#define SO_YY (SO_XX + 48*201)        // 9648
#define SO_DL (SO_YY + 48*201)        // 19296
#define SO_Q  (SO_DL + 48*201)        // 28944 : 48x48 row-major [j][i]
#define SO_V  (SO_Q  + 48*48)         // 31248 : [j][r] stride 132
#define SO_U  (SO_V  + 48*132)        // 37584 : [i][r] stride 132
#define SO_S  (SO_U  + 48*132)        // 43920 : [i][r] stride 132
#define SO_W  (SO_S  + 48*132)        // 50256 : [j][r] stride 132
#define SO_LJ (SO_W  + 48*132)        // 56592 : 384 partials
#define SO_RI (SO_LJ + TPB)           // 56976 : 48 ints (as float slots)
#define SMEM_FLOATS (SO_RI + 64)
#define SMEM_BYTES  (SMEM_FLOATS * 4) // 228,160 B  (<= 227KB opt-in)

__global__ void __launch_bounds__(TPB, 1)
fused_kernel(const float* __restrict__ data, float* __restrict__ out) {
    extern __shared__ float sm[];
    int* ri = (int*)&sm[SO_RI];

    const int tid = threadIdx.x;
    const int k   = blockIdx.x;

    // ---- prologue: load Q, knots, patch row indices --------------------
    {
        const float* gq = g_Q + k * (NSUB * NSUB);
        for (int idx = tid; idx < NSUB * NSUB; idx += TPB) sm[SO_Q + idx] = gq[idx];

        const float* gx = g_xx + (size_t)k * NSUB * MKNOT;
        const float* gy = g_yy + (size_t)k * NSUB * MKNOT;
        const float* gd = g_dl + (size_t)k * NSUB * MKNOT;
        for (int idx = tid; idx < NSUB * MKNOT; idx += TPB) {
            int i = idx / MKNOT;
            int m = idx - i * MKNOT;
            sm[SO_XX + i * 201 + m] = gx[idx];
            sm[SO_YY + i * 201 + m] = gy[idx];
            sm[SO_DL + i * 201 + m] = gd[idx];
        }
        if (tid < NSUB) {
            int nh = k >> 3, nw = k & 7;
            int kh = tid / 12, rem = tid - kh * 12, kw = rem / 3, c = rem - kw * 3;
            int h = (nh * 4 + kh + 2) & 31;
            int w = (nw * 4 + kw + 2) & 31;
            ri[tid] = h * 96 + w * 3 + c;
        }
    }
    __syncthreads();

    const int jg   = tid % 48;        // gather/scatter column
    const int rb   = tid / 48;        // gather/scatter row base (0..7)
    const int tg   = tid >> 5;        // 0..11 : GEMV tile group
    const int rg   = tid & 31;        // 0..31 : GEMV row group
    const int i0   = tg * 4;
    const int r0   = rg * 4;
    const int rsp  = tid & 127;       // spline row
    const int ibas = tid >> 7;        // spline i base (0..2)

    for (int it = 0; it < ITERS; ++it) {
        const int nbase = blockIdx.y * (ROWS_IT * ITERS) + it * ROWS_IT;

        // ---- gather: V[j][r] = data[n, ridx[j]] -------------------------
        {
            const int rid = ri[jg];
#pragma unroll
            for (int t = 0; t < 16; ++t) {
                int r = rb + 8 * t;
                sm[SO_V + jg * 132 + r] = data[(size_t)(nbase + r) * NDIMT + rid];
            }
        }
        __syncthreads();

        // ---- forward GEMV: U[i][r] = sum_j V[j][r] * Q[j][i] -------------
        {
            float a0x=0,a0y=0,a0z=0,a0w=0, a1x=0,a1y=0,a1z=0,a1w=0;
            float a2x=0,a2y=0,a2z=0,a2w=0, a3x=0,a3y=0,a3z=0,a3w=0;
#pragma unroll 8
            for (int j = 0; j < 48; ++j) {
                const float4 q4 = *reinterpret_cast<const float4*>(&sm[SO_Q + j * 48 + i0]);
                const float4 v4 = *reinterpret_cast<const float4*>(&sm[SO_V + j * 132 + r0]);
                a0x += q4.x * v4.x; a0y += q4.x * v4.y; a0z += q4.x * v4.z; a0w += q4.x * v4.w;
                a1x += q4.y * v4.x; a1y += q4.y * v4.y; a1z += q4.y * v4.z; a1w += q4.y * v4.w;
                a2x += q4.z * v4.x; a2y += q4.z * v4.y; a2z += q4.z * v4.z; a2w += q4.z * v4.w;
                a3x += q4.w * v4.x; a3y += q4.w * v4.y; a3z += q4.w * v4.z; a3w += q4.w * v4.w;
            }
            float* u = &sm[SO_U + i0 * 132 + r0];
            u[0]=a0x; u[1]=a0y; u[2]=a0z; u[3]=a0w;  u += 132;
            u[0]=a1x; u[1]=a1y; u[2]=a1z; u[3]=a1w;  u += 132;
            u[0]=a2x; u[1]=a2y; u[2]=a2z; u[3]=a2w;  u += 132;
            u[0]=a3x; u[1]=a3y; u[2]=a3z; u[3]=a3w;
        }
        __syncthreads();

        // ---- RQ spline per coordinate; S = y - u; accumulate log|d| ------
        {
            float ljsum = 0.f;
#pragma unroll 4
            for (int s5 = 0; s5 < 16; ++s5) {
                const int i = ibas + 3 * s5;
                const float* xr = &sm[SO_XX + i * 201];
                const float* yr = &sm[SO_YY + i * 201];
                const float* dr = &sm[SO_DL + i * 201];
                const float x = sm[SO_U + i * 132 + rsp];

                // searchsorted left: first index with xr[idx] >= x
                int lo = 0, hi = MKNOT;
                while (lo < hi) {
                    int mid = (lo + hi) >> 1;
                    if (xr[mid] < x) lo = mid + 1; else hi = mid;
                }

                float yv, dv;
                if (lo == 0) {
                    dv = dr[0];
                    yv = yr[0] + dv * (x - xr[0]);
                } else if (lo == MKNOT) {
                    dv = dr[MKNOT - 1];
                    yv = yr[MKNOT - 1] + dv * (x - xr[MKNOT - 1]);
                } else {
                    const int kk = lo - 1;
                    const float xK = xr[kk], xK1 = xr[kk + 1];
                    const float yK = yr[kk], yK1 = yr[kk + 1];
                    const float dK = dr[kk], dK1 = dr[kk + 1];
                    const float inv = __fdividef(1.f, xK1 - xK);
                    float xi = (x - xK) * inv;
                    xi = fminf(fmaxf(xi, 0.f), 1.f);
                    const float sl  = (yK1 - yK) * inv;
                    const float xi1 = xi * (1.f - xi);
                    const float den = sl + (dK1 + dK - 2.f * sl) * xi1;
                    const float ivd = __fdividef(1.f, den);
                    yv = yK + (yK1 - yK) * (sl * xi * xi + dK * xi1) * ivd;
                    const float om = 1.f - xi;
                    dv = sl * sl * (dK1 * xi * xi + 2.f * sl * xi1 + dK * om * om) * ivd * ivd;
                }
                sm[SO_S + i * 132 + rsp] = yv - x;
                ljsum += __logf(dv);
            }
            sm[SO_LJ + tid] = ljsum;
        }
        __syncthreads();

        // ---- backward GEMV: W[j][r] = sum_i S[i][r] * Q[j][i] ------------
        {
            float a0x=0,a0y=0,a0z=0,a0w=0, a1x=0,a1y=0,a1z=0,a1w=0;
            float a2x=0,a2y=0,a2z=0,a2w=0, a3x=0,a3y=0,a3z=0,a3w=0;
            const int j0 = i0;  // same tile group mapping, now over j
#pragma unroll 8
            for (int i = 0; i < 48; ++i) {
                const float4 s4 = *reinterpret_cast<const float4*>(&sm[SO_S + i * 132 + r0]);
                const float q0 = sm[SO_Q + (j0 + 0) * 48 + i];
                const float q1 = sm[SO_Q + (j0 + 1) * 48 + i];
                const float q2 = sm[SO_Q + (j0 + 2) * 48 + i];
                const float q3 = sm[SO_Q + (j0 + 3) * 48 + i];
                a0x += q0 * s4.x; a0y += q0 * s4.y; a0z += q0 * s4.z; a0w += q0 * s4.w;
                a1x += q1 * s4.x; a1y += q1 * s4.y; a1z += q1 * s4.z; a1w += q1 * s4.w;
                a2x += q2 * s4.x; a2y += q2 * s4.y; a2z += q2 * s4.z; a2w += q2 * s4.w;
                a3x += q3 * s4.x; a3y += q3 * s4.y; a3z += q3 * s4.z; a3w += q3 * s4.w;
            }
            float* w = &sm[SO_W + j0 * 132 + r0];
            w[0]=a0x; w[1]=a0y; w[2]=a0z; w[3]=a0w;  w += 132;
            w[0]=a1x; w[1]=a1y; w[2]=a1z; w[3]=a1w;  w += 132;
            w[0]=a2x; w[1]=a2y; w[2]=a2z; w[3]=a2w;  w += 132;
            w[0]=a3x; w[1]=a3y; w[2]=a3z; w[3]=a3w;
        }
        __syncthreads();

        // ---- scatter: out[n, ridx[j]] = V[j][r] + W[j][r]; logdet partial -
        {
            const int rid = ri[jg];
#pragma unroll
            for (int t = 0; t < 16; ++t) {
                int r = rb + 8 * t;
                out[(size_t)(nbase + r) * NDIMT + rid] =
                    sm[SO_V + jg * 132 + r] + sm[SO_W + jg * 132 + r];
            }
            if (tid < ROWS_IT) {
                g_lj[(size_t)k * NSAMP + nbase + tid] =
                    sm[SO_LJ + tid] + sm[SO_LJ + tid + 128] + sm[SO_LJ + tid + 256];
            }
        }
        __syncthreads();
    }
}

// ---------------------------------------------------------------------------
// Kernel 4: deterministic reduction of per-kernel logdet partials.
// ---------------------------------------------------------------------------
__global__ void reduce_lj(float* __restrict__ logj) {
    int n = blockIdx.x * blockDim.x + threadIdx.x;
    if (n >= NSAMP) return;
    float s = 0.f;
#pragma unroll
    for (int k = 0; k < NKER; ++k) s += g_lj[(size_t)k * NSAMP + n];
    logj[n] = s;
}

// ---------------------------------------------------------------------------
// Launch
// ---------------------------------------------------------------------------
extern "C" void kernel_launch(void* const* d_in, const int* in_sizes, int n_in,
                              void* d_out, int out_size) {
    const float* data     = (const float*)d_in[0];
    const float* A_raw    = (const float*)d_in[1];
    const float* x0       = (const float*)d_in[2];
    const float* logdx    = (const float*)d_in[3];
    const float* y0       = (const float*)d_in[4];
    const float* logdy    = (const float*)d_in[5];
    const float* logderiv = (const float*)d_in[6];

    float* out  = (float*)d_out;
    float* logj = out + (size_t)NSAMP * NDIMT;

    cudaFuncSetAttribute(fused_kernel,
                         cudaFuncAttributeMaxDynamicSharedMemorySize, SMEM_BYTES);

    orth_kernel<<<NKER, 64>>>(A_raw);
    knots_kernel<<<NTRT / 4, 128>>>(x0, logdx, y0, logdy, logderiv);
    fused_kernel<<<dim3(NKER, 16), TPB, SMEM_BYTES>>>(data, out);
    reduce_lj<<<(NSAMP + 255) / 256, 256>>>(logj);
}

// round 6
// speedup vs baseline: 1.1512x; 1.1512x over previous
#include <cuda_runtime.h>
#include <math.h>
#include <stdint.h>

// ---------------------------------------------------------------------------
// Problem constants
// ---------------------------------------------------------------------------
#define NSAMP  8192
#define NDIMT  3072
#define NKER   64
#define NSUB   48
#define MKNOT  200
#define NTRT   3072

// ---------------------------------------------------------------------------
// Device scratch (static only)
// ---------------------------------------------------------------------------
__device__ float g_Q  [NKER * NSUB * NSUB];   // [k][j][i]
__device__ float g_QT [NKER * NSUB * NSUB];   // [k][i][j]
__device__ float g_xx [NTRT * MKNOT];
__device__ float g_yy [NTRT * MKNOT];
__device__ float g_dl [NTRT * MKNOT];
__device__ float g_lj [NKER * NSAMP];
__device__ unsigned char g_lut[NTRT * 256];   // interval-search LUT
__device__ float g_lxlo[NTRT];
__device__ float g_livw[NTRT];

// ---------------------------------------------------------------------------
// f32x2 helpers (sm_103a packed fp32 — exact fp32 per lane)
// ---------------------------------------------------------------------------
__device__ __forceinline__ void ffma2(unsigned long long& acc,
                                      unsigned long long a, unsigned long long b) {
    asm("fma.rn.f32x2 %0, %1, %2, %0;" : "+l"(acc) : "l"(a), "l"(b));
}
__device__ __forceinline__ unsigned long long splat2(float v) {
    unsigned long long r;
    asm("mov.b64 %0, {%1, %1};" : "=l"(r) : "f"(v));
    return r;
}
__device__ __forceinline__ float2 unpk2(unsigned long long v) {
    float2 r;
    asm("mov.b64 {%0, %1}, %2;" : "=f"(r.x), "=f"(r.y) : "l"(v));
    return r;
}

// ---------------------------------------------------------------------------
// Kernel 1: per-patch MGS QR (positive-diagonal), writes Q and Q^T.
// ---------------------------------------------------------------------------
__global__ void orth_kernel(const float* __restrict__ A_raw) {
    const int k   = blockIdx.x;
    const int tid = threadIdx.x;
    __shared__ float qcol[NSUB];

    float col[NSUB];
    const float* Ab = A_raw + k * (NSUB * NSUB);
    if (tid < NSUB) {
#pragma unroll
        for (int r = 0; r < NSUB; ++r) col[r] = Ab[r * NSUB + tid];
    }

    for (int c = 0; c < NSUB; ++c) {
        if (tid == c) {
            float nrm = 0.f;
#pragma unroll
            for (int r = 0; r < NSUB; ++r) nrm += col[r] * col[r];
            float inv = 1.0f / sqrtf(nrm);
#pragma unroll
            for (int r = 0; r < NSUB; ++r) { col[r] *= inv; qcol[r] = col[r]; }
        }
        __syncthreads();
        if (tid < NSUB) {
            if (tid == c) {
                float* gq  = g_Q  + k * (NSUB * NSUB);
                float* gqt = g_QT + k * (NSUB * NSUB);
#pragma unroll
                for (int r = 0; r < NSUB; ++r) {
                    gq [r * NSUB + c] = qcol[r];
                    gqt[c * NSUB + r] = qcol[r];
                }
            } else if (tid > c) {
                float dot = 0.f;
#pragma unroll
                for (int r = 0; r < NSUB; ++r) dot += qcol[r] * col[r];
#pragma unroll
                for (int r = 0; r < NSUB; ++r) col[r] -= dot * qcol[r];
            }
        }
        __syncthreads();
    }
}

// ---------------------------------------------------------------------------
// Kernel 2: knot tables via warp scans.
// ---------------------------------------------------------------------------
__global__ void knots_kernel(const float* __restrict__ x0,
                             const float* __restrict__ logdx,
                             const float* __restrict__ y0,
                             const float* __restrict__ logdy,
                             const float* __restrict__ logderiv) {
    const int warp = (blockIdx.x * blockDim.x + threadIdx.x) >> 5;
    const int lane = threadIdx.x & 31;
    if (warp >= NTRT) return;

    {
        float carry = x0[warp];
        if (lane == 0) g_xx[warp * MKNOT] = carry;
        const float* src = logdx + (size_t)warp * (MKNOT - 1);
        for (int c = 0; c < MKNOT - 1; c += 32) {
            int m = c + lane;
            float v = (m < MKNOT - 1) ? expf(src[m]) : 0.f;
#pragma unroll
            for (int off = 1; off < 32; off <<= 1) {
                float o = __shfl_up_sync(0xffffffffu, v, off);
                if (lane >= off) v += o;
            }
            if (m < MKNOT - 1) g_xx[warp * MKNOT + m + 1] = carry + v;
            carry += __shfl_sync(0xffffffffu, v, 31);
        }
    }
    {
        float carry = y0[warp];
        if (lane == 0) g_yy[warp * MKNOT] = carry;
        const float* src = logdy + (size_t)warp * (MKNOT - 1);
        for (int c = 0; c < MKNOT - 1; c += 32) {
            int m = c + lane;
            float v = (m < MKNOT - 1) ? expf(src[m]) : 0.f;
#pragma unroll
            for (int off = 1; off < 32; off <<= 1) {
                float o = __shfl_up_sync(0xffffffffu, v, off);
                if (lane >= off) v += o;
            }
            if (m < MKNOT - 1) g_yy[warp * MKNOT + m + 1] = carry + v;
            carry += __shfl_sync(0xffffffffu, v, 31);
        }
    }
    for (int m = lane; m < MKNOT; m += 32)
        g_dl[warp * MKNOT + m] = expf(logderiv[(size_t)warp * MKNOT + m]);
}

// ---------------------------------------------------------------------------
// Kernel 2b: per-coordinate 256-bin search LUT (separate launch => g_xx visible)
// ---------------------------------------------------------------------------
__global__ void lut_kernel() {
    const int warp = (blockIdx.x * blockDim.x + threadIdx.x) >> 5;
    const int lane = threadIdx.x & 31;
    if (warp >= NTRT) return;
    const float* xr = g_xx + (size_t)warp * MKNOT;
    float xlo = xr[0], xhi = xr[MKNOT - 1];
    float binw = (xhi - xlo) * (1.0f / 256.0f);
    if (lane == 0) { g_lxlo[warp] = xlo; g_livw[warp] = 256.0f / (xhi - xlo); }
#pragma unroll
    for (int t = 0; t < 8; ++t) {
        int q = lane + 32 * t;
        float L = xlo + q * binw;
        int lo = 0, hi = MKNOT;
        while (lo < hi) { int mid = (lo + hi) >> 1; if (xr[mid] < L) lo = mid + 1; else hi = mid; }
        g_lut[(size_t)warp * 256 + q] = (unsigned char)lo;
    }
}

// ---------------------------------------------------------------------------
// Kernel 3: fused gather -> GEMV(f32x2) -> spline(LUT) -> GEMV(f32x2) -> scatter
// ---------------------------------------------------------------------------
#define TPB      384
#define ROWS_IT  128
#define ITERS    4
#define RST      134                   // padded row stride (2-way banks max)

// smem layout (float offsets) — all float4-aligned
#define SO_XX  0                       // 48*200
#define SO_YY  (SO_XX + 48*200)        // 9600
#define SO_DL  (SO_YY + 48*200)        // 19200
#define SO_Q   (SO_DL + 48*200)        // 28800 : [j][i]
#define SO_QT  (SO_Q  + 48*48)         // 31104 : [i][j]
#define SO_V   (SO_QT + 48*48)         // 33408
#define SO_U   (SO_V  + 48*RST)        // 39840 (S written in-place)
#define SO_W   (SO_U  + 48*RST)        // 46272
#define SO_LJ  (SO_W  + 48*RST)        // 52704 : [ig*128 + r], 768
#define SO_XLO (SO_LJ + 768)           // 53472 : 48
#define SO_IVW (SO_XLO + 48)           // 53520 : 48
#define SO_RI  (SO_IVW + 48)           // 53568 : 48 ints
#define SO_LUT (SO_RI + 48)            // 53616 : 3072 float-slots (uint8[12288])
#define SMEM_FLOATS (SO_LUT + 3072)    // 56688
#define SMEM_BYTES  (SMEM_FLOATS * 4)  // 226,752 B

__device__ __forceinline__ float rq_eval(float x,
                                         const float* __restrict__ xr,
                                         const float* __restrict__ yr,
                                         const float* __restrict__ dr,
                                         const unsigned char* __restrict__ lut,
                                         float xlo, float ivw, float& ld) {
    int q = __float2int_rd((x - xlo) * ivw);
    q = min(max(q, 0), 255);
    int idx = lut[q];
    while (idx > 0 && xr[idx - 1] >= x) --idx;      // guard (float-edge safety)
    while (idx < MKNOT && xr[idx] < x) ++idx;       // short forward scan
    if (idx == 0) {
        float d = dr[0]; ld = __logf(d);
        return yr[0] + d * (x - xr[0]);
    }
    if (idx == MKNOT) {
        float d = dr[MKNOT - 1]; ld = __logf(d);
        return yr[MKNOT - 1] + d * (x - xr[MKNOT - 1]);
    }
    const int kk = idx - 1;
    const float xK = xr[kk], xK1 = xr[kk + 1];
    const float yK = yr[kk], yK1 = yr[kk + 1];
    const float dK = dr[kk], dK1 = dr[kk + 1];
    const float inv = __fdividef(1.f, xK1 - xK);
    float xi = fminf(fmaxf((x - xK) * inv, 0.f), 1.f);
    const float sl  = (yK1 - yK) * inv;
    const float xi1 = xi * (1.f - xi);
    const float den = sl + (dK1 + dK - 2.f * sl) * xi1;
    const float ivd = __fdividef(1.f, den);
    const float om  = 1.f - xi;
    ld = __logf(sl * sl * (dK1 * xi * xi + 2.f * sl * xi1 + dK * om * om) * ivd * ivd);
    return yK + (yK1 - yK) * (sl * xi * xi + dK * xi1) * ivd;
}

__global__ void __launch_bounds__(TPB, 1)
fused_kernel(const float* __restrict__ data, float* __restrict__ out) {
    extern __shared__ float sm[];
    int* ri = (int*)&sm[SO_RI];
    unsigned char* slut = (unsigned char*)&sm[SO_LUT];

    const int tid = threadIdx.x;
    const int k   = blockIdx.x;

    // ---- prologue --------------------------------------------------------
    {
        const float4* gq  = (const float4*)(g_Q  + k * (NSUB * NSUB));
        const float4* gqt = (const float4*)(g_QT + k * (NSUB * NSUB));
        float4* sq  = (float4*)&sm[SO_Q];
        float4* sqt = (float4*)&sm[SO_QT];
        for (int idx = tid; idx < NSUB * NSUB / 4; idx += TPB) {
            sq[idx]  = gq[idx];
            sqt[idx] = gqt[idx];
        }
        const float4* gx = (const float4*)(g_xx + (size_t)k * NSUB * MKNOT);
        const float4* gy = (const float4*)(g_yy + (size_t)k * NSUB * MKNOT);
        const float4* gd = (const float4*)(g_dl + (size_t)k * NSUB * MKNOT);
        float4* sx = (float4*)&sm[SO_XX];
        float4* sy = (float4*)&sm[SO_YY];
        float4* sd = (float4*)&sm[SO_DL];
        for (int idx = tid; idx < NSUB * MKNOT / 4; idx += TPB) {
            sx[idx] = gx[idx]; sy[idx] = gy[idx]; sd[idx] = gd[idx];
        }
        const int4* gl = (const int4*)(g_lut + (size_t)k * NSUB * 256);
        int4* sl = (int4*)slut;
        for (int idx = tid; idx < NSUB * 256 / 16; idx += TPB) sl[idx] = gl[idx];
        if (tid < NSUB) {
            sm[SO_XLO + tid] = g_lxlo[k * NSUB + tid];
            sm[SO_IVW + tid] = g_livw[k * NSUB + tid];
            int nh = k >> 3, nw = k & 7;
            int kh = tid / 12, rem = tid - kh * 12, kw = rem / 3, c = rem - kw * 3;
            int h = (nh * 4 + kh + 2) & 31;
            int w = (nw * 4 + kw + 2) & 31;
            ri[tid] = h * 96 + w * 3 + c;
        }
    }
    __syncthreads();

    const int jg = tid % 48;          // gather/scatter
    const int rb = tid / 48;
    const int tg = tid >> 6;          // 0..5 : GEMV / spline i-group
    const int rg = tid & 63;          // 0..63 : r-pair group
    const int i0 = tg * 8;
    const int r0 = rg * 2;

    for (int it = 0; it < ITERS; ++it) {
        const int nbase = blockIdx.y * (ROWS_IT * ITERS) + it * ROWS_IT;

        // ---- gather ------------------------------------------------------
        {
            const int rid = ri[jg];
#pragma unroll
            for (int t = 0; t < 16; ++t) {
                int r = rb + 8 * t;
                sm[SO_V + jg * RST + r] = __ldg(&data[(size_t)(nbase + r) * NDIMT + rid]);
            }
        }
        __syncthreads();

        // ---- forward GEMV: U[i][r] = sum_j Q[j][i] * V[j][r]  (f32x2, i-pairs)
        {
            unsigned long long acc[4][2] = {{0ull,0ull},{0ull,0ull},{0ull,0ull},{0ull,0ull}};
#pragma unroll 8
            for (int j = 0; j < 48; ++j) {
                ulonglong2 qa = *(const ulonglong2*)&sm[SO_Q + j * 48 + i0];     // (i0,i0+1),(i0+2,i0+3)
                ulonglong2 qb = *(const ulonglong2*)&sm[SO_Q + j * 48 + i0 + 4];
                float2 v = *(const float2*)&sm[SO_V + j * RST + r0];
                unsigned long long va = splat2(v.x), vb = splat2(v.y);
                ffma2(acc[0][0], qa.x, va); ffma2(acc[0][1], qa.x, vb);
                ffma2(acc[1][0], qa.y, va); ffma2(acc[1][1], qa.y, vb);
                ffma2(acc[2][0], qb.x, va); ffma2(acc[2][1], qb.x, vb);
                ffma2(acc[3][0], qb.y, va); ffma2(acc[3][1], qb.y, vb);
            }
#pragma unroll
            for (int p = 0; p < 4; ++p) {
                float2 a0 = unpk2(acc[p][0]);   // (i0+2p, i0+2p+1) @ r0
                float2 a1 = unpk2(acc[p][1]);   //   "               @ r0+1
                sm[SO_U + (i0 + 2*p    ) * RST + r0    ] = a0.x;
                sm[SO_U + (i0 + 2*p + 1) * RST + r0    ] = a0.y;
                sm[SO_U + (i0 + 2*p    ) * RST + r0 + 1] = a1.x;
                sm[SO_U + (i0 + 2*p + 1) * RST + r0 + 1] = a1.y;
            }
        }
        __syncthreads();

        // ---- RQ spline (LUT search), S = y - u written in-place over U ----
        {
            float lja = 0.f, ljb = 0.f;
#pragma unroll
            for (int s = 0; s < 8; ++s) {
                const int i = i0 + s;
                const float* xr = &sm[SO_XX + i * MKNOT];
                const float* yr = &sm[SO_YY + i * MKNOT];
                const float* dr = &sm[SO_DL + i * MKNOT];
                const unsigned char* lut = slut + i * 256;
                const float xlo = sm[SO_XLO + i];
                const float ivw = sm[SO_IVW + i];

                float2 xv = *(const float2*)&sm[SO_U + i * RST + r0];
                float la, lb;
                float ya = rq_eval(xv.x, xr, yr, dr, lut, xlo, ivw, la);
                float yb = rq_eval(xv.y, xr, yr, dr, lut, xlo, ivw, lb);
                float2 sv; sv.x = ya - xv.x; sv.y = yb - xv.y;
                *(float2*)&sm[SO_U + i * RST + r0] = sv;
                lja += la; ljb += lb;
            }
            float2 lj2; lj2.x = lja; lj2.y = ljb;
            *(float2*)&sm[SO_LJ + tg * 128 + r0] = lj2;
        }
        __syncthreads();

        // ---- backward GEMV: W[j][r] = sum_i QT[i][j] * S[i][r]  (f32x2, j-pairs)
        {
            unsigned long long acc[4][2] = {{0ull,0ull},{0ull,0ull},{0ull,0ull},{0ull,0ull}};
            const int j0 = i0;
#pragma unroll 8
            for (int i = 0; i < 48; ++i) {
                ulonglong2 qa = *(const ulonglong2*)&sm[SO_QT + i * 48 + j0];
                ulonglong2 qb = *(const ulonglong2*)&sm[SO_QT + i * 48 + j0 + 4];
                float2 v = *(const float2*)&sm[SO_U + i * RST + r0];
                unsigned long long va = splat2(v.x), vb = splat2(v.y);
                ffma2(acc[0][0], qa.x, va); ffma2(acc[0][1], qa.x, vb);
                ffma2(acc[1][0], qa.y, va); ffma2(acc[1][1], qa.y, vb);
                ffma2(acc[2][0], qb.x, va); ffma2(acc[2][1], qb.x, vb);
                ffma2(acc[3][0], qb.y, va); ffma2(acc[3][1], qb.y, vb);
            }
#pragma unroll
            for (int p = 0; p < 4; ++p) {
                float2 a0 = unpk2(acc[p][0]);
                float2 a1 = unpk2(acc[p][1]);
                sm[SO_W + (j0 + 2*p    ) * RST + r0    ] = a0.x;
                sm[SO_W + (j0 + 2*p + 1) * RST + r0    ] = a0.y;
                sm[SO_W + (j0 + 2*p    ) * RST + r0 + 1] = a1.x;
                sm[SO_W + (j0 + 2*p + 1) * RST + r0 + 1] = a1.y;
            }
        }
        __syncthreads();

        // ---- scatter + per-row logdet partials ----------------------------
        {
            const int rid = ri[jg];
#pragma unroll
            for (int t = 0; t < 16; ++t) {
                int r = rb + 8 * t;
                out[(size_t)(nbase + r) * NDIMT + rid] =
                    sm[SO_V + jg * RST + r] + sm[SO_W + jg * RST + r];
            }
            if (tid < ROWS_IT) {
                float s = 0.f;
#pragma unroll
                for (int g = 0; g < 6; ++g) s += sm[SO_LJ + g * 128 + tid];
                g_lj[(size_t)k * NSAMP + nbase + tid] = s;
            }
        }
        __syncthreads();
    }
}

// ---------------------------------------------------------------------------
// Kernel 4: deterministic logdet reduction.
// ---------------------------------------------------------------------------
__global__ void reduce_lj(float* __restrict__ logj) {
    int n = blockIdx.x * blockDim.x + threadIdx.x;
    if (n >= NSAMP) return;
    float s = 0.f;
#pragma unroll
    for (int k = 0; k < NKER; ++k) s += g_lj[(size_t)k * NSAMP + n];
    logj[n] = s;
}

// ---------------------------------------------------------------------------
// Launch
// ---------------------------------------------------------------------------
extern "C" void kernel_launch(void* const* d_in, const int* in_sizes, int n_in,
                              void* d_out, int out_size) {
    const float* data     = (const float*)d_in[0];
    const float* A_raw    = (const float*)d_in[1];
    const float* x0       = (const float*)d_in[2];
    const float* logdx    = (const float*)d_in[3];
    const float* y0       = (const float*)d_in[4];
    const float* logdy    = (const float*)d_in[5];
    const float* logderiv = (const float*)d_in[6];

    float* out  = (float*)d_out;
    float* logj = out + (size_t)NSAMP * NDIMT;

    cudaFuncSetAttribute(fused_kernel,
                         cudaFuncAttributeMaxDynamicSharedMemorySize, SMEM_BYTES);

    orth_kernel<<<NKER, 64>>>(A_raw);
    knots_kernel<<<NTRT / 4, 128>>>(x0, logdx, y0, logdy, logderiv);
    lut_kernel<<<NTRT / 8, 256>>>();
    fused_kernel<<<dim3(NKER, 16), TPB, SMEM_BYTES>>>(data, out);
    reduce_lj<<<(NSAMP + 255) / 256, 256>>>(logj);
}

// round 7
// speedup vs baseline: 1.2753x; 1.1078x over previous
#include <cuda_runtime.h>
#include <math.h>
#include <stdint.h>

// ---------------------------------------------------------------------------
// Problem constants
// ---------------------------------------------------------------------------
#define NSAMP  8192
#define NDIMT  3072
#define NKER   64
#define NSUB   48
#define MKNOT  200
#define NTRT   3072

// ---------------------------------------------------------------------------
// Device scratch (static only)
// ---------------------------------------------------------------------------
__device__ float g_Q  [NKER * NSUB * NSUB];   // [k][j][i]
__device__ float g_QT [NKER * NSUB * NSUB];   // [k][i][j]
__device__ float g_xx [NTRT * MKNOT];
__device__ float g_yy [NTRT * MKNOT];
__device__ float g_dl [NTRT * MKNOT];
__device__ float g_lj [NKER * NSAMP];
__device__ unsigned char g_lut[NTRT * 256];
__device__ float g_lxlo[NTRT];
__device__ float g_livw[NTRT];

// ---------------------------------------------------------------------------
// f32x2 helpers (packed fp32 — exact fp32 per lane)
// ---------------------------------------------------------------------------
__device__ __forceinline__ void ffma2(unsigned long long& acc,
                                      unsigned long long a, unsigned long long b) {
    asm("fma.rn.f32x2 %0, %1, %2, %0;" : "+l"(acc) : "l"(a), "l"(b));
}
__device__ __forceinline__ unsigned long long splat2(float v) {
    unsigned long long r;
    asm("mov.b64 %0, {%1, %1};" : "=l"(r) : "f"(v));
    return r;
}
__device__ __forceinline__ float2 unpk2(unsigned long long v) {
    float2 r;
    asm("mov.b64 {%0, %1}, %2;" : "=f"(r.x), "=f"(r.y) : "l"(v));
    return r;
}

// ---------------------------------------------------------------------------
// Kernel 1: per-patch MGS QR (positive diagonal), writes Q and Q^T.
// ---------------------------------------------------------------------------
__global__ void orth_kernel(const float* __restrict__ A_raw) {
    const int k   = blockIdx.x;
    const int tid = threadIdx.x;
    __shared__ float qcol[NSUB];

    float col[NSUB];
    const float* Ab = A_raw + k * (NSUB * NSUB);
    if (tid < NSUB) {
#pragma unroll
        for (int r = 0; r < NSUB; ++r) col[r] = Ab[r * NSUB + tid];
    }

    for (int c = 0; c < NSUB; ++c) {
        if (tid == c) {
            float nrm = 0.f;
#pragma unroll
            for (int r = 0; r < NSUB; ++r) nrm += col[r] * col[r];
            float inv = 1.0f / sqrtf(nrm);
#pragma unroll
            for (int r = 0; r < NSUB; ++r) { col[r] *= inv; qcol[r] = col[r]; }
        }
        __syncthreads();
        if (tid < NSUB) {
            if (tid == c) {
                float* gq  = g_Q  + k * (NSUB * NSUB);
                float* gqt = g_QT + k * (NSUB * NSUB);
#pragma unroll
                for (int r = 0; r < NSUB; ++r) {
                    gq [r * NSUB + c] = qcol[r];
                    gqt[c * NSUB + r] = qcol[r];
                }
            } else if (tid > c) {
                float dot = 0.f;
#pragma unroll
                for (int r = 0; r < NSUB; ++r) dot += qcol[r] * col[r];
#pragma unroll
                for (int r = 0; r < NSUB; ++r) col[r] -= dot * qcol[r];
            }
        }
        __syncthreads();
    }
}

// ---------------------------------------------------------------------------
// Kernel 2: knot tables via warp scans.
// ---------------------------------------------------------------------------
__global__ void knots_kernel(const float* __restrict__ x0,
                             const float* __restrict__ logdx,
                             const float* __restrict__ y0,
                             const float* __restrict__ logdy,
                             const float* __restrict__ logderiv) {
    const int warp = (blockIdx.x * blockDim.x + threadIdx.x) >> 5;
    const int lane = threadIdx.x & 31;
    if (warp >= NTRT) return;

    {
        float carry = x0[warp];
        if (lane == 0) g_xx[warp * MKNOT] = carry;
        const float* src = logdx + (size_t)warp * (MKNOT - 1);
        for (int c = 0; c < MKNOT - 1; c += 32) {
            int m = c + lane;
            float v = (m < MKNOT - 1) ? expf(src[m]) : 0.f;
#pragma unroll
            for (int off = 1; off < 32; off <<= 1) {
                float o = __shfl_up_sync(0xffffffffu, v, off);
                if (lane >= off) v += o;
            }
            if (m < MKNOT - 1) g_xx[warp * MKNOT + m + 1] = carry + v;
            carry += __shfl_sync(0xffffffffu, v, 31);
        }
    }
    {
        float carry = y0[warp];
        if (lane == 0) g_yy[warp * MKNOT] = carry;
        const float* src = logdy + (size_t)warp * (MKNOT - 1);
        for (int c = 0; c < MKNOT - 1; c += 32) {
            int m = c + lane;
            float v = (m < MKNOT - 1) ? expf(src[m]) : 0.f;
#pragma unroll
            for (int off = 1; off < 32; off <<= 1) {
                float o = __shfl_up_sync(0xffffffffu, v, off);
                if (lane >= off) v += o;
            }
            if (m < MKNOT - 1) g_yy[warp * MKNOT + m + 1] = carry + v;
            carry += __shfl_sync(0xffffffffu, v, 31);
        }
    }
    for (int m = lane; m < MKNOT; m += 32)
        g_dl[warp * MKNOT + m] = expf(logderiv[(size_t)warp * MKNOT + m]);
}

// ---------------------------------------------------------------------------
// Kernel 2b: per-coordinate 256-bin search LUT.
// ---------------------------------------------------------------------------
__global__ void lut_kernel() {
    const int warp = (blockIdx.x * blockDim.x + threadIdx.x) >> 5;
    const int lane = threadIdx.x & 31;
    if (warp >= NTRT) return;
    const float* xr = g_xx + (size_t)warp * MKNOT;
    float xlo = xr[0], xhi = xr[MKNOT - 1];
    float binw = (xhi - xlo) * (1.0f / 256.0f);
    if (lane == 0) { g_lxlo[warp] = xlo; g_livw[warp] = 256.0f / (xhi - xlo); }
#pragma unroll
    for (int t = 0; t < 8; ++t) {
        int q = lane + 32 * t;
        float L = xlo + q * binw;
        int lo = 0, hi = MKNOT;
        while (lo < hi) { int mid = (lo + hi) >> 1; if (xr[mid] < L) lo = mid + 1; else hi = mid; }
        g_lut[(size_t)warp * 256 + q] = (unsigned char)lo;
    }
}

// ---------------------------------------------------------------------------
// Kernel 3: fused pipeline. 768 threads, 24 warps, 1 CTA/SM.
// ---------------------------------------------------------------------------
#define TPB      768
#define ROWS_IT  128
#define ITERS    4
#define RST      130                   // padded row stride (2-way worst case)

// smem layout (float offsets)
#define SO_XX  0                       // 9600
#define SO_YY  (SO_XX + 48*200)        // 9600
#define SO_DL  (SO_YY + 48*200)        // 19200
#define SO_Q   (SO_DL + 48*200)        // 28800 : [j][i]
#define SO_QT  (SO_Q  + 48*48)         // 31104 : [i][j]
#define SO_V   (SO_QT + 48*48)         // 33408
#define SO_U   (SO_V  + 48*RST)        // 39648 (S in-place)
#define SO_W   (SO_U  + 48*RST)        // 45888
#define SO_LJ  (SO_W  + 48*RST)        // 52128 : [12][128]
#define SO_XLO (SO_LJ + 12*128)        // 53664
#define SO_IVW (SO_XLO + 48)           // 53712
#define SO_RI  (SO_IVW + 48)           // 53760
#define SO_LUT (SO_RI + 48)            // 53808 : uint8[12288]
#define SMEM_FLOATS (SO_LUT + 3072)    // 56880
#define SMEM_BYTES  (SMEM_FLOATS * 4)  // 227,520 B

__device__ __forceinline__ float rq_eval(float x,
                                         const float* __restrict__ xr,
                                         const float* __restrict__ yr,
                                         const float* __restrict__ dr,
                                         const unsigned char* __restrict__ lut,
                                         float xlo, float ivw, float& dv) {
    int q = __float2int_rd((x - xlo) * ivw);
    q = min(max(q, 0), 255);
    int idx = lut[q];
    while (idx > 0 && xr[idx - 1] >= x) --idx;
    while (idx < MKNOT && xr[idx] < x) ++idx;
    if (idx == 0) {
        dv = dr[0];
        return yr[0] + dv * (x - xr[0]);
    }
    if (idx == MKNOT) {
        dv = dr[MKNOT - 1];
        return yr[MKNOT - 1] + dv * (x - xr[MKNOT - 1]);
    }
    const int kk = idx - 1;
    const float xK = xr[kk], xK1 = xr[kk + 1];
    const float yK = yr[kk], yK1 = yr[kk + 1];
    const float dK = dr[kk], dK1 = dr[kk + 1];
    const float inv = __fdividef(1.f, xK1 - xK);
    float xi = fminf(fmaxf((x - xK) * inv, 0.f), 1.f);
    const float sl  = (yK1 - yK) * inv;
    const float xi1 = xi * (1.f - xi);
    const float den = sl + (dK1 + dK - 2.f * sl) * xi1;
    const float ivd = __fdividef(1.f, den);
    const float om  = 1.f - xi;
    dv = sl * sl * (dK1 * xi * xi + 2.f * sl * xi1 + dK * om * om) * ivd * ivd;
    return yK + (yK1 - yK) * (sl * xi * xi + dK * xi1) * ivd;
}

__global__ void __launch_bounds__(TPB, 1)
fused_kernel(const float* __restrict__ data, float* __restrict__ out) {
    extern __shared__ float sm[];
    int* ri = (int*)&sm[SO_RI];
    unsigned char* slut = (unsigned char*)&sm[SO_LUT];

    const int tid = threadIdx.x;
    const int k   = blockIdx.x;

    // ---- prologue --------------------------------------------------------
    {
        const float4* gq  = (const float4*)(g_Q  + k * (NSUB * NSUB));
        const float4* gqt = (const float4*)(g_QT + k * (NSUB * NSUB));
        float4* sq  = (float4*)&sm[SO_Q];
        float4* sqt = (float4*)&sm[SO_QT];
        for (int idx = tid; idx < NSUB * NSUB / 4; idx += TPB) {
            sq[idx]  = gq[idx];
            sqt[idx] = gqt[idx];
        }
        const float4* gx = (const float4*)(g_xx + (size_t)k * NSUB * MKNOT);
        const float4* gy = (const float4*)(g_yy + (size_t)k * NSUB * MKNOT);
        const float4* gd = (const float4*)(g_dl + (size_t)k * NSUB * MKNOT);
        float4* sx = (float4*)&sm[SO_XX];
        float4* sy = (float4*)&sm[SO_YY];
        float4* sd = (float4*)&sm[SO_DL];
        for (int idx = tid; idx < NSUB * MKNOT / 4; idx += TPB) {
            sx[idx] = gx[idx]; sy[idx] = gy[idx]; sd[idx] = gd[idx];
        }
        const int4* gl = (const int4*)(g_lut + (size_t)k * NSUB * 256);
        int4* sl = (int4*)slut;
        for (int idx = tid; idx < NSUB * 256 / 16; idx += TPB) sl[idx] = gl[idx];
        if (tid < NSUB) {
            sm[SO_XLO + tid] = g_lxlo[k * NSUB + tid];
            sm[SO_IVW + tid] = g_livw[k * NSUB + tid];
            int nh = k >> 3, nw = k & 7;
            int kh = tid / 12, rem = tid - kh * 12, kw = rem / 3, c = rem - kw * 3;
            int h = (nh * 4 + kh + 2) & 31;
            int w = (nw * 4 + kw + 2) & 31;
            ri[tid] = h * 96 + w * 3 + c;
        }
    }
    __syncthreads();

    const int jg = tid % 48;          // gather/scatter column
    const int rb = tid / 48;          // 0..15
    const int ig = tid >> 6;          // 0..11 : i/j tile group (4 wide)
    const int rg = tid & 63;          // 0..63 : r pair group
    const int i0 = ig * 4;
    const int r0 = rg * 2;

    for (int it = 0; it < ITERS; ++it) {
        const int nbase = blockIdx.y * (ROWS_IT * ITERS) + it * ROWS_IT;

        // ---- gather: V[j][r] = data[n, ridx[j]] ---------------------------
        {
            const int rid = ri[jg];
#pragma unroll
            for (int t = 0; t < 8; ++t) {
                int r = rb + 16 * t;
                sm[SO_V + jg * RST + r] = __ldg(&data[(size_t)(nbase + r) * NDIMT + rid]);
            }
        }
        __syncthreads();

        // ---- forward GEMV: U[i][r] = sum_j Q[j][i] * V[j][r] (r-packed) ---
        {
            unsigned long long a0 = 0, a1 = 0, a2 = 0, a3 = 0;
#pragma unroll 8
            for (int j = 0; j < 48; ++j) {
                const float4 q = *(const float4*)&sm[SO_Q + j * 48 + i0];  // broadcast
                const unsigned long long v = *(const unsigned long long*)&sm[SO_V + j * RST + r0];
                ffma2(a0, splat2(q.x), v);
                ffma2(a1, splat2(q.y), v);
                ffma2(a2, splat2(q.z), v);
                ffma2(a3, splat2(q.w), v);
            }
            *(float2*)&sm[SO_U + (i0 + 0) * RST + r0] = unpk2(a0);
            *(float2*)&sm[SO_U + (i0 + 1) * RST + r0] = unpk2(a1);
            *(float2*)&sm[SO_U + (i0 + 2) * RST + r0] = unpk2(a2);
            *(float2*)&sm[SO_U + (i0 + 3) * RST + r0] = unpk2(a3);
        }
        __syncthreads();

        // ---- RQ spline (LUT search); S = y - u in-place; logdet ----------
        {
            float pa = 1.f, pb = 1.f;
#pragma unroll
            for (int s = 0; s < 4; ++s) {
                const int i = i0 + s;
                const float* xr = &sm[SO_XX + i * MKNOT];
                const float* yr = &sm[SO_YY + i * MKNOT];
                const float* dr = &sm[SO_DL + i * MKNOT];
                const unsigned char* lut = slut + i * 256;
                const float xlo = sm[SO_XLO + i];
                const float ivw = sm[SO_IVW + i];

                float2 xv = *(const float2*)&sm[SO_U + i * RST + r0];
                float da, db;
                float ya = rq_eval(xv.x, xr, yr, dr, lut, xlo, ivw, da);
                float yb = rq_eval(xv.y, xr, yr, dr, lut, xlo, ivw, db);
                float2 sv; sv.x = ya - xv.x; sv.y = yb - xv.y;
                *(float2*)&sm[SO_U + i * RST + r0] = sv;
                pa *= da; pb *= db;
            }
            float2 lj2; lj2.x = __logf(pa); lj2.y = __logf(pb);
            *(float2*)&sm[SO_LJ + ig * 128 + r0] = lj2;
        }
        __syncthreads();

        // ---- backward GEMV: W[j][r] = sum_i QT[i][j] * S[i][r] ------------
        {
            unsigned long long a0 = 0, a1 = 0, a2 = 0, a3 = 0;
            const int j0 = i0;
#pragma unroll 8
            for (int i = 0; i < 48; ++i) {
                const float4 q = *(const float4*)&sm[SO_QT + i * 48 + j0];
                const unsigned long long v = *(const unsigned long long*)&sm[SO_U + i * RST + r0];
                ffma2(a0, splat2(q.x), v);
                ffma2(a1, splat2(q.y), v);
                ffma2(a2, splat2(q.z), v);
                ffma2(a3, splat2(q.w), v);
            }
            *(float2*)&sm[SO_W + (j0 + 0) * RST + r0] = unpk2(a0);
            *(float2*)&sm[SO_W + (j0 + 1) * RST + r0] = unpk2(a1);
            *(float2*)&sm[SO_W + (j0 + 2) * RST + r0] = unpk2(a2);
            *(float2*)&sm[SO_W + (j0 + 3) * RST + r0] = unpk2(a3);
        }
        __syncthreads();

        // ---- scatter + per-row logdet partials ----------------------------
        {
            const int rid = ri[jg];
#pragma unroll
            for (int t = 0; t < 8; ++t) {
                int r = rb + 16 * t;
                out[(size_t)(nbase + r) * NDIMT + rid] =
                    sm[SO_V + jg * RST + r] + sm[SO_W + jg * RST + r];
            }
            if (tid < ROWS_IT) {
                float s = 0.f;
#pragma unroll
                for (int g = 0; g < 12; ++g) s += sm[SO_LJ + g * 128 + tid];
                g_lj[(size_t)k * NSAMP + nbase + tid] = s;
            }
        }
        __syncthreads();
    }
}

// ---------------------------------------------------------------------------
// Kernel 4: deterministic logdet reduction.
// ---------------------------------------------------------------------------
__global__ void reduce_lj(float* __restrict__ logj) {
    int n = blockIdx.x * blockDim.x + threadIdx.x;
    if (n >= NSAMP) return;
    float s = 0.f;
#pragma unroll
    for (int k = 0; k < NKER; ++k) s += g_lj[(size_t)k * NSAMP + n];
    logj[n] = s;
}

// ---------------------------------------------------------------------------
// Launch
// ---------------------------------------------------------------------------
extern "C" void kernel_launch(void* const* d_in, const int* in_sizes, int n_in,
                              void* d_out, int out_size) {
    const float* data     = (const float*)d_in[0];
    const float* A_raw    = (const float*)d_in[1];
    const float* x0       = (const float*)d_in[2];
    const float* logdx    = (const float*)d_in[3];
    const float* y0       = (const float*)d_in[4];
    const float* logdy    = (const float*)d_in[5];
    const float* logderiv = (const float*)d_in[6];

    float* out  = (float*)d_out;
    float* logj = out + (size_t)NSAMP * NDIMT;

    cudaFuncSetAttribute(fused_kernel,
                         cudaFuncAttributeMaxDynamicSharedMemorySize, SMEM_BYTES);

    orth_kernel<<<NKER, 64>>>(A_raw);
    knots_kernel<<<NTRT / 4, 128>>>(x0, logdx, y0, logdy, logderiv);
    lut_kernel<<<NTRT / 8, 256>>>();
    fused_kernel<<<dim3(NKER, 16), TPB, SMEM_BYTES>>>(data, out);
    reduce_lj<<<(NSAMP + 255) / 256, 256>>>(logj);
}